// round 9
// baseline (speedup 1.0000x reference)
#include <cuda_runtime.h>
#include <cuda_bf16.h>
#include <cstdint>
#include <cstddef>

// Problem constants
#define B_ 64
#define S_ 512
#define E_ 256
#define H_ 512

// Scan decomposition: 16 clusters x 8 CTAs; each cluster owns 4 batch rows,
// each CTA owns 64 rows of W_hh resident in shared memory for all 512 steps.
#define BT_ 16     // batch tiles (clusters)
#define BC_ 4      // batch rows per cluster
#define CL_ 8      // CTAs per cluster (j-dimension split: 8 * 64 = 512)
#define JL_ 64     // W_hh rows per CTA
#define WPITCH_ 513  // padded row pitch (odd -> conflict-free column reads)

// ---------------------------------------------------------------------------
// Device scratch (no allocations allowed)
// ---------------------------------------------------------------------------
__device__ float g_pre[(size_t)B_ * S_ * H_];   // pre-activations (reused per layer)
__device__ float g_y0[(size_t)B_ * S_ * H_];    // layer-0 outputs
__device__ float4 g_hbuf[2][BT_ * H_];          // double-buffered h: [buf][bt*512+k] -> 4 batch lanes

__device__ __forceinline__ void cluster_sync_() {
    // arrive has .release / wait has .acquire semantics at cluster scope:
    // orders the __stcg h-writes before peers' __ldcg h-reads.
    asm volatile("barrier.cluster.arrive.aligned;" ::: "memory");
    asm volatile("barrier.cluster.wait.aligned;" ::: "memory");
}

// ---------------------------------------------------------------------------
// GEMM: C[m,n] = sum_k Arow(m)[k] * W[n,k] + ba[n] + bb[n]
// Arow(m) = idx ? emb[idx[m]] : A[m]   (fused embedding gather)
// Tiles: 64x64x16, 256 threads, 4x4 microtile, k-major shared layout.
// M, N, K all divide the tile sizes for this problem (no bounds checks).
// ---------------------------------------------------------------------------
__global__ void __launch_bounds__(256) gemm_tn_kernel(
    const float* __restrict__ A, const int* __restrict__ idx, int lda,
    const float* __restrict__ W, const float* __restrict__ ba,
    const float* __restrict__ bb, float* __restrict__ C, int N, int K)
{
    __shared__ float As[16][68];
    __shared__ float Bs[16][68];
    __shared__ int srcs[64];

    const int tid = threadIdx.x;
    const int m0 = blockIdx.y * 64;
    const int n0 = blockIdx.x * 64;

    if (idx != nullptr && tid < 64) srcs[tid] = idx[m0 + tid];
    __syncthreads();

    const int lm = tid >> 2;          // 0..63 : row within tile this thread loads
    const int lk = (tid & 3) * 4;     // 0,4,8,12 : k offset (float4)
    const float* arow = (idx != nullptr) ? (A + (size_t)srcs[lm] * (size_t)lda)
                                         : (A + (size_t)(m0 + lm) * (size_t)lda);
    const float* brow = W + (size_t)(n0 + lm) * (size_t)K;

    const int iy = tid >> 4;          // 0..15 : micro-row group
    const int ix = tid & 15;          // 0..15 : micro-col group

    float acc[4][4] = {};

    for (int k0 = 0; k0 < K; k0 += 16) {
        float4 av = *(const float4*)(arow + k0 + lk);
        float4 bv = *(const float4*)(brow + k0 + lk);
        __syncthreads();   // previous compute done before overwrite
        As[lk + 0][lm] = av.x; As[lk + 1][lm] = av.y;
        As[lk + 2][lm] = av.z; As[lk + 3][lm] = av.w;
        Bs[lk + 0][lm] = bv.x; Bs[lk + 1][lm] = bv.y;
        Bs[lk + 2][lm] = bv.z; Bs[lk + 3][lm] = bv.w;
        __syncthreads();
#pragma unroll
        for (int k = 0; k < 16; ++k) {
            float4 a = *(const float4*)&As[k][iy * 4];
            float4 b = *(const float4*)&Bs[k][ix * 4];
            acc[0][0] += a.x * b.x; acc[0][1] += a.x * b.y;
            acc[0][2] += a.x * b.z; acc[0][3] += a.x * b.w;
            acc[1][0] += a.y * b.x; acc[1][1] += a.y * b.y;
            acc[1][2] += a.y * b.z; acc[1][3] += a.y * b.w;
            acc[2][0] += a.z * b.x; acc[2][1] += a.z * b.y;
            acc[2][2] += a.z * b.z; acc[2][3] += a.z * b.w;
            acc[3][0] += a.w * b.x; acc[3][1] += a.w * b.y;
            acc[3][2] += a.w * b.z; acc[3][3] += a.w * b.w;
        }
    }

    const int n = n0 + ix * 4;
    const float4 bias = make_float4(ba[n] + bb[n], ba[n + 1] + bb[n + 1],
                                    ba[n + 2] + bb[n + 2], ba[n + 3] + bb[n + 3]);
#pragma unroll
    for (int r = 0; r < 4; ++r) {
        float4 o = make_float4(acc[r][0] + bias.x, acc[r][1] + bias.y,
                               acc[r][2] + bias.z, acc[r][3] + bias.w);
        *(float4*)&C[(size_t)(m0 + iy * 4 + r) * (size_t)N + n] = o;
    }
}

// ---------------------------------------------------------------------------
// Recurrent scan: h_t = tanh(pre[:,t,:] + h_{t-1} @ W_hh^T)
// Grid (CL_, BT_), cluster (CL_,1,1), 256 threads.
// Thread mapping: jl = tid & 63 (output row within this CTA's W slice),
//                 ks = tid >> 6 (k-quarter, 128 k's each) -> 4-way k-split
//                 reduced through shared memory.
// h tile lives in shared as float4[k] (4 batch lanes), exchanged between
// cluster CTAs via L2 (stcg/ldcg) with cluster barrier each step.
// ---------------------------------------------------------------------------
__global__ void __launch_bounds__(256, 1) __cluster_dims__(CL_, 1, 1)
rnn_scan_kernel(const float* __restrict__ pre, const float* __restrict__ Whh,
                float* __restrict__ y, float* __restrict__ hlast)
{
    extern __shared__ float smem[];
    float4* h_sh4 = (float4*)smem;                        // 512 float4 (8 KB)
    float*  W_sh  = smem + 2048;                          // 64 x 513 (128.25 KB)
    float4* red4  = (float4*)(smem + 2048 + JL_ * WPITCH_); // 3 x 64 float4 (3 KB)

    const int tid  = threadIdx.x;
    const int rank = blockIdx.x;   // 0..7  (j slice)
    const int bt   = blockIdx.y;   // 0..15 (batch tile)

    // Load this CTA's 64 rows of W_hh into shared (once for all 512 steps).
    for (int i = tid; i < JL_ * H_; i += 256) {
        const int jl = i >> 9;         // /512
        const int k  = i & (H_ - 1);
        W_sh[jl * WPITCH_ + k] = Whh[(size_t)(rank * JL_ + jl) * H_ + k];
    }
    // h_0 = 0
    for (int i = tid; i < H_; i += 256) h_sh4[i] = make_float4(0.f, 0.f, 0.f, 0.f);
    __syncthreads();

    const int jl = tid & 63;
    const int ks = tid >> 6;
    const int jg = rank * JL_ + jl;
    const float*  wrow = W_sh + jl * WPITCH_ + ks * 128;
    const float4* hp   = h_sh4 + ks * 128;
    float4* const hg0 = &g_hbuf[0][bt * H_];
    float4* const hg1 = &g_hbuf[1][bt * H_];

    for (int t = 0; t < S_; ++t) {
        float a0 = 0.f, a1 = 0.f, a2 = 0.f, a3 = 0.f;
#pragma unroll 8
        for (int k = 0; k < 128; ++k) {
            const float  w  = wrow[k];
            const float4 h4 = hp[k];
            a0 += w * h4.x; a1 += w * h4.y; a2 += w * h4.z; a3 += w * h4.w;
        }
        if (ks) red4[(ks - 1) * 64 + jl] = make_float4(a0, a1, a2, a3);
        __syncthreads();
        if (ks == 0) {
            const float4 r0 = red4[jl];
            const float4 r1 = red4[64 + jl];
            const float4 r2 = red4[128 + jl];
            const size_t base = ((size_t)(bt * BC_) * S_ + t) * H_ + jg;
            const size_t str  = (size_t)S_ * H_;
            const float v0 = tanhf(a0 + r0.x + r1.x + r2.x + __ldg(&pre[base]));
            const float v1 = tanhf(a1 + r0.y + r1.y + r2.y + __ldg(&pre[base + str]));
            const float v2 = tanhf(a2 + r0.z + r1.z + r2.z + __ldg(&pre[base + 2 * str]));
            const float v3 = tanhf(a3 + r0.w + r1.w + r2.w + __ldg(&pre[base + 3 * str]));
            y[base]           = v0;
            y[base + str]     = v1;
            y[base + 2 * str] = v2;
            y[base + 3 * str] = v3;
            const float4 hv = make_float4(v0, v1, v2, v3);
            __stcg(((t & 1) ? hg1 : hg0) + jg, hv);
            if (t == S_ - 1) {
                hlast[(size_t)(bt * BC_ + 0) * H_ + jg] = v0;
                hlast[(size_t)(bt * BC_ + 1) * H_ + jg] = v1;
                hlast[(size_t)(bt * BC_ + 2) * H_ + jg] = v2;
                hlast[(size_t)(bt * BC_ + 3) * H_ + jg] = v3;
            }
        }
        cluster_sync_();   // release h-writes / acquire for peers' reads
        if (t < S_ - 1) {
            const float4* src4 = (t & 1) ? hg1 : hg0;
            for (int i = tid; i < H_; i += 256) h_sh4[i] = __ldcg(src4 + i);
            __syncthreads();
        }
    }
}

// ---------------------------------------------------------------------------
// Launch
// Inputs: src, emb, W_ih0, W_hh0, b_ih0, b_hh0, W_ih1, W_hh1, b_ih1, b_hh1
// Output: y1 [B,S,H] followed by hidden [2,B,H]
// ---------------------------------------------------------------------------
extern "C" void kernel_launch(void* const* d_in, const int* in_sizes, int n_in,
                              void* d_out, int out_size)
{
    (void)in_sizes; (void)n_in; (void)out_size;
    const int*   src  = (const int*)d_in[0];
    const float* emb  = (const float*)d_in[1];
    const float* Wih0 = (const float*)d_in[2];
    const float* Whh0 = (const float*)d_in[3];
    const float* bih0 = (const float*)d_in[4];
    const float* bhh0 = (const float*)d_in[5];
    const float* Wih1 = (const float*)d_in[6];
    const float* Whh1 = (const float*)d_in[7];
    const float* bih1 = (const float*)d_in[8];
    const float* bhh1 = (const float*)d_in[9];

    float* out = (float*)d_out;
    float* y1  = out;
    float* hid = out + (size_t)B_ * S_ * H_;

    float *pre = nullptr, *y0 = nullptr;
    cudaGetSymbolAddress((void**)&pre, g_pre);
    cudaGetSymbolAddress((void**)&y0,  g_y0);

    const size_t scan_smem = (size_t)(2048 + JL_ * WPITCH_ + 3 * 64 * 4) * sizeof(float);
    cudaFuncSetAttribute(rnn_scan_kernel,
                         cudaFuncAttributeMaxDynamicSharedMemorySize, (int)scan_smem);

    const dim3 blk(256);
    const dim3 gemm_grid(H_ / 64, (B_ * S_) / 64);
    const dim3 scan_grid(CL_, BT_);

    // Layer 0: fused embedding-gather GEMM -> pre, then scan -> y0, h_last0
    gemm_tn_kernel<<<gemm_grid, blk>>>(emb, src, E_, Wih0, bih0, bhh0, pre, H_, E_);
    rnn_scan_kernel<<<scan_grid, blk, scan_smem>>>(pre, Whh0, y0, hid);

    // Layer 1: plain GEMM -> pre (reused), then scan -> y1 (d_out), h_last1
    gemm_tn_kernel<<<gemm_grid, blk>>>(y0, nullptr, H_, Wih1, bih1, bhh1, pre, H_, H_);
    rnn_scan_kernel<<<scan_grid, blk, scan_smem>>>(pre, Whh1, y1, hid + (size_t)B_ * H_);
}

// round 10
// speedup vs baseline: 1.2412x; 1.2412x over previous
#include <cuda_runtime.h>
#include <cuda_bf16.h>
#include <cstdint>
#include <cstddef>

// Problem constants
#define B_ 64
#define S_ 512
#define E_ 256
#define H_ 512

// Scan decomposition: 16 clusters x 8 CTAs; each cluster owns 4 batch rows,
// each CTA owns 64 rows of W_hh resident in shared memory for all 512 steps.
#define BT_ 16     // batch tiles (clusters)
#define BC_ 4      // batch rows per cluster
#define CL_ 8      // CTAs per cluster (j split: 8 * 64 = 512)
#define JL_ 64     // W_hh rows per CTA
#define WP_ 516    // W pitch in floats: 516 mod 32 = 4 -> conflict-free LDS.128 columns

typedef unsigned long long u64;

// ---------------------------------------------------------------------------
// Packed fp32x2 helpers (Blackwell FFMA2 path: 2x fp32 throughput, full IEEE)
// ---------------------------------------------------------------------------
__device__ __forceinline__ u64 splat2(float x) {
    u64 r; asm("mov.b64 %0, {%1, %1};" : "=l"(r) : "f"(x)); return r;
}
__device__ __forceinline__ void fma2(u64& d, u64 a, u64 b) {
    asm("fma.rn.f32x2 %0, %1, %2, %0;" : "+l"(d) : "l"(a), "l"(b));
}
__device__ __forceinline__ void add2(u64& d, u64 a) {
    asm("add.rn.f32x2 %0, %1, %0;" : "+l"(d) : "l"(a));
}
__device__ __forceinline__ void unpack2(u64 v, float& lo, float& hi) {
    asm("mov.b64 {%0, %1}, %2;" : "=f"(lo), "=f"(hi) : "l"(v));
}

// Fast tanh: 2 MUFU ops, abs error ~1e-7 (vs 1e-3 budget). Large |x| -> exp=inf -> 1.
__device__ __forceinline__ float fast_tanh(float x) {
    float ax = fabsf(x);
    float e  = __expf(ax + ax);
    float r  = 1.0f - __fdividef(2.0f, e + 1.0f);
    return copysignf(r, x);
}

// ---------------------------------------------------------------------------
// Device scratch (no allocations allowed)
// ---------------------------------------------------------------------------
__device__ float g_pre[(size_t)B_ * S_ * H_];   // pre-activations (reused per layer)
__device__ float g_y0[(size_t)B_ * S_ * H_];    // layer-0 outputs
__device__ float4 g_hbuf[2][BT_ * H_];          // double-buffered h exchange via L2

__device__ __forceinline__ void cluster_sync_() {
    // arrive(.release) / wait(.acquire) at cluster scope: orders the __stcg
    // h-writes before peers' __ldcg h-reads. Also a full intra-CTA barrier.
    asm volatile("barrier.cluster.arrive.aligned;" ::: "memory");
    asm volatile("barrier.cluster.wait.aligned;" ::: "memory");
}

// ---------------------------------------------------------------------------
// GEMM: C[m,n] = sum_k Arow(m)[k] * W[n,k] + ba[n] + bb[n]
// Arow(m) = idx ? emb[idx[m]] : A[m]   (fused embedding gather)
// 128x128x16 tile, 256 threads, 8x8 microtile, packed f32x2 accumulators.
// M=32768, N=512, K in {256,512}: all divide tile sizes (no bounds checks).
// ---------------------------------------------------------------------------
__global__ void __launch_bounds__(256) gemm_tn_kernel(
    const float* __restrict__ A, const int* __restrict__ idx, int lda,
    const float* __restrict__ W, const float* __restrict__ ba,
    const float* __restrict__ bb, float* __restrict__ C, int N, int K)
{
    __shared__ float As[16][136];
    __shared__ float Bs[16][136];
    __shared__ int srcs[128];

    const int tid = threadIdx.x;
    const int m0 = blockIdx.y * 128;
    const int n0 = blockIdx.x * 128;

    if (idx != nullptr && tid < 128) srcs[tid] = idx[m0 + tid];
    __syncthreads();

    const int lm = tid >> 1;          // 0..127 : row this thread loads
    const int lk = (tid & 1) * 8;     // 0 or 8 : k offset (two float4s)
    const float* arow = (idx != nullptr) ? (A + (size_t)srcs[lm] * (size_t)lda)
                                         : (A + (size_t)(m0 + lm) * (size_t)lda);
    const float* brow = W + (size_t)(n0 + lm) * (size_t)K;

    const int iy = tid >> 4;          // 0..15 : row group (8 rows)
    const int ix = tid & 15;          // 0..15 : col group (8 cols = 4 f32x2)

    u64 acc[8][4];
#pragma unroll
    for (int r = 0; r < 8; ++r)
#pragma unroll
        for (int c = 0; c < 4; ++c) acc[r][c] = 0ull;

    for (int k0 = 0; k0 < K; k0 += 16) {
        float4 av0 = *(const float4*)(arow + k0 + lk);
        float4 av1 = *(const float4*)(arow + k0 + lk + 4);
        float4 bv0 = *(const float4*)(brow + k0 + lk);
        float4 bv1 = *(const float4*)(brow + k0 + lk + 4);
        __syncthreads();   // previous compute done before overwrite
        As[lk + 0][lm] = av0.x; As[lk + 1][lm] = av0.y;
        As[lk + 2][lm] = av0.z; As[lk + 3][lm] = av0.w;
        As[lk + 4][lm] = av1.x; As[lk + 5][lm] = av1.y;
        As[lk + 6][lm] = av1.z; As[lk + 7][lm] = av1.w;
        Bs[lk + 0][lm] = bv0.x; Bs[lk + 1][lm] = bv0.y;
        Bs[lk + 2][lm] = bv0.z; Bs[lk + 3][lm] = bv0.w;
        Bs[lk + 4][lm] = bv1.x; Bs[lk + 5][lm] = bv1.y;
        Bs[lk + 6][lm] = bv1.z; Bs[lk + 7][lm] = bv1.w;
        __syncthreads();
#pragma unroll
        for (int k = 0; k < 16; ++k) {
            float4 a0 = *(const float4*)&As[k][iy * 8];
            float4 a1 = *(const float4*)&As[k][iy * 8 + 4];
            // b pairs load naturally packed: (n,n+1) -> one u64
            ulonglong2 bq0 = *(const ulonglong2*)&Bs[k][ix * 8];
            ulonglong2 bq1 = *(const ulonglong2*)&Bs[k][ix * 8 + 4];
            u64 s;
            s = splat2(a0.x);
            fma2(acc[0][0], s, bq0.x); fma2(acc[0][1], s, bq0.y);
            fma2(acc[0][2], s, bq1.x); fma2(acc[0][3], s, bq1.y);
            s = splat2(a0.y);
            fma2(acc[1][0], s, bq0.x); fma2(acc[1][1], s, bq0.y);
            fma2(acc[1][2], s, bq1.x); fma2(acc[1][3], s, bq1.y);
            s = splat2(a0.z);
            fma2(acc[2][0], s, bq0.x); fma2(acc[2][1], s, bq0.y);
            fma2(acc[2][2], s, bq1.x); fma2(acc[2][3], s, bq1.y);
            s = splat2(a0.w);
            fma2(acc[3][0], s, bq0.x); fma2(acc[3][1], s, bq0.y);
            fma2(acc[3][2], s, bq1.x); fma2(acc[3][3], s, bq1.y);
            s = splat2(a1.x);
            fma2(acc[4][0], s, bq0.x); fma2(acc[4][1], s, bq0.y);
            fma2(acc[4][2], s, bq1.x); fma2(acc[4][3], s, bq1.y);
            s = splat2(a1.y);
            fma2(acc[5][0], s, bq0.x); fma2(acc[5][1], s, bq0.y);
            fma2(acc[5][2], s, bq1.x); fma2(acc[5][3], s, bq1.y);
            s = splat2(a1.z);
            fma2(acc[6][0], s, bq0.x); fma2(acc[6][1], s, bq0.y);
            fma2(acc[6][2], s, bq1.x); fma2(acc[6][3], s, bq1.y);
            s = splat2(a1.w);
            fma2(acc[7][0], s, bq0.x); fma2(acc[7][1], s, bq0.y);
            fma2(acc[7][2], s, bq1.x); fma2(acc[7][3], s, bq1.y);
        }
    }

    const int n = n0 + ix * 8;
    float bias[8];
#pragma unroll
    for (int c = 0; c < 8; ++c) bias[c] = ba[n + c] + bb[n + c];

#pragma unroll
    for (int r = 0; r < 8; ++r) {
        float v[8];
#pragma unroll
        for (int c = 0; c < 4; ++c) unpack2(acc[r][c], v[2 * c], v[2 * c + 1]);
        float4 o0 = make_float4(v[0] + bias[0], v[1] + bias[1], v[2] + bias[2], v[3] + bias[3]);
        float4 o1 = make_float4(v[4] + bias[4], v[5] + bias[5], v[6] + bias[6], v[7] + bias[7]);
        float* crow = C + (size_t)(m0 + iy * 8 + r) * (size_t)N + n;
        *(float4*)(crow)     = o0;
        *(float4*)(crow + 4) = o1;
    }
}

// ---------------------------------------------------------------------------
// Recurrent scan: h_t = tanh(pre[:,t,:] + h_{t-1} @ W_hh^T)
// Grid (CL_, BT_), cluster (CL_,1,1), 512 threads (16 warps).
// Thread map: jl = tid & 63 (output row in this CTA's W slice),
//             ks = tid >> 6 (0..7, 64-k slice) -> 8-way k-split, reduced in smem.
// h lives in shared as float4[k] (4 batch lanes packed -> 2 f32x2 per k),
// exchanged between cluster CTAs via L2 (stcg/ldcg) + cluster barrier per step.
// ---------------------------------------------------------------------------
__global__ void __launch_bounds__(512, 1) __cluster_dims__(CL_, 1, 1)
rnn_scan_kernel(const float* __restrict__ pre, const float* __restrict__ Whh,
                float* __restrict__ y, float* __restrict__ hlast)
{
    extern __shared__ float smem[];
    float4* h_sh4 = (float4*)smem;                       // 512 float4 (8 KB)
    float*  W_sh  = smem + 2048;                         // 64 x 516 (129 KB)
    float4* red4  = (float4*)(smem + 2048 + JL_ * WP_);  // 7 x 64 float4 (7 KB)

    const int tid  = threadIdx.x;
    const int rank = blockIdx.x;   // 0..7  (j slice)
    const int bt   = blockIdx.y;   // 0..15 (batch tile)

    // Load this CTA's 64 rows of W_hh into shared (once, reused 512 steps).
    for (int i = tid; i < JL_ * H_; i += 512) {
        const int jl = i >> 9;          // /512
        const int k  = i & (H_ - 1);
        W_sh[jl * WP_ + k] = Whh[(size_t)(rank * JL_ + jl) * H_ + k];
    }
    h_sh4[tid] = make_float4(0.f, 0.f, 0.f, 0.f);   // h_0 = 0
    __syncthreads();

    const int jl = tid & 63;
    const int ks = tid >> 6;
    const int jg = rank * JL_ + jl;
    const float*  wrow = W_sh + jl * WP_ + ks * 64;
    const float4* hp   = h_sh4 + ks * 64;
    float4* const hg0 = &g_hbuf[0][bt * H_];
    float4* const hg1 = &g_hbuf[1][bt * H_];
    const size_t str  = (size_t)S_ * H_;

    for (int t = 0; t < S_; ++t) {
        // Prefetch pre[t] for the tail (DRAM latency hidden under compute).
        float p0 = 0.f, p1 = 0.f, p2 = 0.f, p3 = 0.f;
        const size_t base = ((size_t)(bt * BC_) * S_ + t) * (size_t)H_ + jg;
        if (ks == 0) {
            p0 = __ldg(&pre[base]);
            p1 = __ldg(&pre[base + str]);
            p2 = __ldg(&pre[base + 2 * str]);
            p3 = __ldg(&pre[base + 3 * str]);
        }

        u64 acc01 = 0ull, acc23 = 0ull;   // (b0,b1) and (b2,b3) lanes
#pragma unroll
        for (int kk = 0; kk < 16; ++kk) {
            float4 w4 = *(const float4*)(wrow + kk * 4);
            const ulonglong2* hq = (const ulonglong2*)(hp + kk * 4);
            u64 s;
            s = splat2(w4.x); fma2(acc01, s, hq[0].x); fma2(acc23, s, hq[0].y);
            s = splat2(w4.y); fma2(acc01, s, hq[1].x); fma2(acc23, s, hq[1].y);
            s = splat2(w4.z); fma2(acc01, s, hq[2].x); fma2(acc23, s, hq[2].y);
            s = splat2(w4.w); fma2(acc01, s, hq[3].x); fma2(acc23, s, hq[3].y);
        }

        if (ks) {
            float a0, a1, a2, a3;
            unpack2(acc01, a0, a1); unpack2(acc23, a2, a3);
            red4[(ks - 1) * 64 + jl] = make_float4(a0, a1, a2, a3);
        }
        __syncthreads();

        if (ks == 0) {
#pragma unroll
            for (int g = 0; g < 7; ++g) {
                ulonglong2 r = *(const ulonglong2*)&red4[g * 64 + jl];
                add2(acc01, r.x); add2(acc23, r.y);
            }
            float a0, a1, a2, a3;
            unpack2(acc01, a0, a1); unpack2(acc23, a2, a3);
            const float v0 = fast_tanh(a0 + p0);
            const float v1 = fast_tanh(a1 + p1);
            const float v2 = fast_tanh(a2 + p2);
            const float v3 = fast_tanh(a3 + p3);
            y[base]           = v0;
            y[base + str]     = v1;
            y[base + 2 * str] = v2;
            y[base + 3 * str] = v3;
            __stcg(((t & 1) ? hg1 : hg0) + jg, make_float4(v0, v1, v2, v3));
            if (t == S_ - 1) {
                hlast[(size_t)(bt * BC_ + 0) * H_ + jg] = v0;
                hlast[(size_t)(bt * BC_ + 1) * H_ + jg] = v1;
                hlast[(size_t)(bt * BC_ + 2) * H_ + jg] = v2;
                hlast[(size_t)(bt * BC_ + 3) * H_ + jg] = v3;
            }
        }
        cluster_sync_();   // release h-writes / acquire for peers' reads
        if (t < S_ - 1) {
            const float4* src4 = (t & 1) ? hg1 : hg0;
            h_sh4[tid] = __ldcg(src4 + tid);    // one LDG.128 per thread
            __syncthreads();
        }
    }
}

// ---------------------------------------------------------------------------
// Launch
// Inputs: src, emb, W_ih0, W_hh0, b_ih0, b_hh0, W_ih1, W_hh1, b_ih1, b_hh1
// Output: y1 [B,S,H] followed by hidden [2,B,H]
// ---------------------------------------------------------------------------
extern "C" void kernel_launch(void* const* d_in, const int* in_sizes, int n_in,
                              void* d_out, int out_size)
{
    (void)in_sizes; (void)n_in; (void)out_size;
    const int*   src  = (const int*)d_in[0];
    const float* emb  = (const float*)d_in[1];
    const float* Wih0 = (const float*)d_in[2];
    const float* Whh0 = (const float*)d_in[3];
    const float* bih0 = (const float*)d_in[4];
    const float* bhh0 = (const float*)d_in[5];
    const float* Wih1 = (const float*)d_in[6];
    const float* Whh1 = (const float*)d_in[7];
    const float* bih1 = (const float*)d_in[8];
    const float* bhh1 = (const float*)d_in[9];

    float* out = (float*)d_out;
    float* y1  = out;
    float* hid = out + (size_t)B_ * S_ * H_;

    float *pre = nullptr, *y0 = nullptr;
    cudaGetSymbolAddress((void**)&pre, g_pre);
    cudaGetSymbolAddress((void**)&y0,  g_y0);

    const size_t scan_smem = (size_t)(2048 + JL_ * WP_ + 7 * 64 * 4) * sizeof(float);
    cudaFuncSetAttribute(rnn_scan_kernel,
                         cudaFuncAttributeMaxDynamicSharedMemorySize, (int)scan_smem);

    const dim3 gemm_blk(256);
    const dim3 scan_blk(512);
    const dim3 gemm_grid(H_ / 128, (B_ * S_) / 128);
    const dim3 scan_grid(CL_, BT_);

    // Layer 0: fused embedding-gather GEMM -> pre, then scan -> y0, h_last0
    gemm_tn_kernel<<<gemm_grid, gemm_blk>>>(emb, src, E_, Wih0, bih0, bhh0, pre, H_, E_);
    rnn_scan_kernel<<<scan_grid, scan_blk, scan_smem>>>(pre, Whh0, y0, hid);

    // Layer 1: plain GEMM -> pre (reused), then scan -> y1 (d_out), h_last1
    gemm_tn_kernel<<<gemm_grid, gemm_blk>>>(y0, nullptr, H_, Wih1, bih1, bhh1, pre, H_, H_);
    rnn_scan_kernel<<<scan_grid, scan_blk, scan_smem>>>(pre, Whh1, y1, hid + (size_t)B_ * H_);
}